// round 13
// baseline (speedup 1.0000x reference)
#include <cuda_runtime.h>
#include <cuda_fp16.h>
#include <math.h>
#include <stdint.h>

#define B_   2
#define S_   2048
#define H_   2048
#define NH_  16
#define HD_  128
#define NE_  8
#define I_   4096
#define T_   (B_*S_)
#define EPS_ 1e-5f
#define ATT_SCALE 0.08838834764831845f

// -------------------- scratch --------------------
__device__ float  g_att[(size_t)B_*NH_*S_*S_];     // fp32 scores
__device__ float  g_hg [(size_t)NE_*T_*I_];        // aliased: P(half) during attn
__device__ float  g_rex[(size_t)T_*H_];            // ln2 exact (router)
__device__ __half g_q16  [(size_t)T_*H_];
__device__ __half g_k16  [(size_t)T_*H_];
__device__ __half g_vt16 [(size_t)B_*NH_*HD_*S_];  // V transposed: [b,h][d][s]
__device__ __half g_xn16 [(size_t)T_*H_];
__device__ __half g_ao16 [(size_t)T_*H_];
__device__ __half g_xn216[(size_t)T_*H_];
__device__ __half g_hg16 [(size_t)NE_*T_*I_];      // swiglu out (down A)
#define OFF_WQ ((size_t)0)
#define OFF_WK ((size_t)H_*H_)
#define OFF_WV ((size_t)2*H_*H_)
#define OFF_WO ((size_t)3*H_*H_)
#define OFF_WG ((size_t)4*H_*H_)
#define OFF_WU (OFF_WG + (size_t)NE_*I_*H_)
#define OFF_WD (OFF_WU + (size_t)NE_*I_*H_)
#define W16_TOTAL (OFF_WD + (size_t)NE_*H_*I_)
__device__ __half g_w16[W16_TOTAL];
__device__ int   g_tok[NE_*T_];
__device__ float g_wt [NE_*T_];
__device__ int   g_cnt[NE_];

// -------------------- helpers --------------------
__device__ __forceinline__ void mma16h(float* c, const uint32_t* a, uint32_t b0, uint32_t b1) {
    asm volatile("mma.sync.aligned.m16n8k16.row.col.f32.f16.f16.f32 "
        "{%0,%1,%2,%3},{%4,%5,%6,%7},{%8,%9},{%0,%1,%2,%3};"
        : "+f"(c[0]), "+f"(c[1]), "+f"(c[2]), "+f"(c[3])
        : "r"(a[0]), "r"(a[1]), "r"(a[2]), "r"(a[3]), "r"(b0), "r"(b1));
}
__device__ __forceinline__ void ldsm4(uint32_t* r, uint32_t addr) {
    asm volatile("ldmatrix.sync.aligned.m8n8.x4.shared.b16 {%0,%1,%2,%3},[%4];"
        : "=r"(r[0]), "=r"(r[1]), "=r"(r[2]), "=r"(r[3]) : "r"(addr));
}
__device__ __forceinline__ void cpa16(uint32_t dst, const void* src) {
    asm volatile("cp.async.cg.shared.global [%0], [%1], 16;" :: "r"(dst), "l"(src));
}
__device__ __forceinline__ void cpa_commit() { asm volatile("cp.async.commit_group;"); }
__device__ __forceinline__ void cpa_wait1()  { asm volatile("cp.async.wait_group 1;" ::: "memory"); }
__device__ __forceinline__ uint32_t smem_u32(const void* p) {
    uint32_t a; asm("{ .reg .u64 t; cvta.to.shared.u64 t, %1; cvt.u32.u64 %0, t; }"
                    : "=r"(a) : "l"(p));
    return a;
}

#define HROWB 80
#define H_STG 3
#define H_STAGE (128*HROWB)
#define H_SMEM (2*H_STG*H_STAGE)      // 61440 B
#define GU_SMEM (3*H_STG*H_STAGE)     // 92160 B (A + Bg + Bu)

// -------------------- small kernels --------------------
__global__ void zero_cnt_k() { if (threadIdx.x < NE_) g_cnt[threadIdx.x] = 0; }

__global__ void cvt16_k(const float* __restrict__ s, __half* __restrict__ d, size_t n8) {
    size_t stride = (size_t)gridDim.x * blockDim.x;
    const float4* S = (const float4*)s;
    uint4* D = (uint4*)d;
    for (size_t i = (size_t)blockIdx.x * blockDim.x + threadIdx.x; i < n8; i += stride) {
        float4 v0 = S[2 * i], v1 = S[2 * i + 1];
        __half2 h0 = __floats2half2_rn(v0.x, v0.y);
        __half2 h1 = __floats2half2_rn(v0.z, v0.w);
        __half2 h2 = __floats2half2_rn(v1.x, v1.y);
        __half2 h3 = __floats2half2_rn(v1.z, v1.w);
        uint4 o;
        o.x = *(const uint32_t*)&h0;
        o.y = *(const uint32_t*)&h1;
        o.z = *(const uint32_t*)&h2;
        o.w = *(const uint32_t*)&h3;
        D[i] = o;
    }
}

__global__ void rmsnorm_k(const float* __restrict__ x, const float* __restrict__ w,
                          __half* __restrict__ o16, float* __restrict__ o_exact) {
    int t = blockIdx.x;
    const float* xr = x + (size_t)t * H_;
    float s = 0.f;
    for (int j = threadIdx.x; j < H_; j += blockDim.x) { float v = xr[j]; s += v * v; }
    __shared__ float red[32];
    for (int off = 16; off; off >>= 1) s += __shfl_xor_sync(0xffffffffu, s, off);
    if ((threadIdx.x & 31) == 0) red[threadIdx.x >> 5] = s;
    __syncthreads();
    if (threadIdx.x < 32) {
        float v = (threadIdx.x < (blockDim.x >> 5)) ? red[threadIdx.x] : 0.f;
        for (int off = 16; off; off >>= 1) v += __shfl_xor_sync(0xffffffffu, v, off);
        if (threadIdx.x == 0) red[0] = v;
    }
    __syncthreads();
    float inv = rsqrtf(red[0] / (float)H_ + EPS_);
    __half* orow = o16 + (size_t)t * H_;
    if (o_exact) {
        float* erow = o_exact + (size_t)t * H_;
        for (int j = threadIdx.x; j < H_; j += blockDim.x) {
            float v = xr[j] * inv * w[j];
            erow[j] = v;
            orow[j] = __float2half_rn(v);
        }
    } else {
        for (int j = threadIdx.x; j < H_; j += blockDim.x)
            orow[j] = __float2half_rn(xr[j] * inv * w[j]);
    }
}

// ==================== fp16 MMA GEMM (general) ====================
struct GArgs {
    const __half* A;
    const __half* B0; const __half* B1; const __half* B2;
    float* C0;
    __half* H0; __half* H1; __half* H2;
    const float* resid;
    int M, N, K, lda, ldb, ldc;
    const int* tok; const float* wt; const int* cntp;
    size_t aStride, bStride, cStride;
    int mode;
    int qkv;
};

__global__ void __launch_bounds__(256, 2)
hgemm(const GArgs args) {
    int z = blockIdx.z;
    const __half* A = args.A;
    const __half* B;
    const int* a_idx = nullptr; const int* c_idx = nullptr; const float* c_w = nullptr;
    int cnt = args.M;
    int ep_mode;          // 0=fp32 (resid opt), 1=half H, 2=vtrans, 3=atomic
    float* Cf = args.C0;
    __half* Ch = nullptr;

    if (args.mode == 0) {
        B = (z == 0) ? args.B0 : (z == 1 ? args.B1 : args.B2);
        if (args.qkv) {
            if (z < 2) { Ch = z ? args.H1 : args.H0; ep_mode = 1; }
            else ep_mode = 2;
        } else ep_mode = 0;
    } else {
        int e = z;
        A = args.A + (size_t)e * args.aStride;
        B = args.B0 + (size_t)e * args.bStride;
        c_idx = args.tok + e * T_;
        c_w = args.wt + e * T_;
        cnt = args.cntp[e];
        ep_mode = 3;
    }

    int m0 = blockIdx.y * 128, n0 = blockIdx.x * 128;
    if (m0 >= cnt) return;

    extern __shared__ char smem[];
    uint32_t sA = smem_u32(smem);
    uint32_t sB = sA + H_STG * H_STAGE;

    int tid = threadIdx.x;
    int lane = tid & 31, w = tid >> 5;
    int wm = (w & 3) * 32, wn = (w >> 2) * 64;

    int lrow = tid >> 2;
    int lch  = tid & 3;
    const __half* gA[2]; const __half* gB[2];
    uint32_t stA[2], stB[2];
#pragma unroll
    for (int rr = 0; rr < 2; rr++) {
        int r = lrow + rr * 64;
        int mr = m0 + r;
        int grow = a_idx ? ((mr < cnt) ? a_idx[mr] : 0) : mr;
        gA[rr] = A + (size_t)grow * args.lda + lch * 8;
        gB[rr] = B + (size_t)(n0 + r) * args.ldb + lch * 8;
        stA[rr] = sA + r * HROWB + lch * 16;
        stB[rr] = sB + r * HROWB + lch * 16;
    }

    uint32_t aAddr = sA + (wm + (lane & 15)) * HROWB + ((lane >> 4) & 1) * 16;
    uint32_t bAddr = sB + (wn + (lane & 7) + 8 * ((lane >> 4) & 1)) * HROWB
                        + ((lane >> 3) & 1) * 16;

    float acc[2][8][4];
#pragma unroll
    for (int i = 0; i < 2; i++)
#pragma unroll
        for (int j = 0; j < 8; j++)
#pragma unroll
            for (int q = 0; q < 4; q++) acc[i][j][q] = 0.f;

    int nk = args.K / 32;

#pragma unroll
    for (int s = 0; s < 2; s++) {
#pragma unroll
        for (int rr = 0; rr < 2; rr++) {
            cpa16(stA[rr] + s * H_STAGE, gA[rr] + s * 32);
            cpa16(stB[rr] + s * H_STAGE, gB[rr] + s * 32);
        }
        cpa_commit();
    }

    for (int kt = 0; kt < nk; kt++) {
        cpa_wait1();
        __syncthreads();
        if (kt + 2 < nk) {
            int kb = (kt + 2) * 32;
            uint32_t off = ((kt + 2) % H_STG) * H_STAGE;
#pragma unroll
            for (int rr = 0; rr < 2; rr++) {
                cpa16(stA[rr] + off, gA[rr] + kb);
                cpa16(stB[rr] + off, gB[rr] + kb);
            }
        }
        cpa_commit();

        uint32_t soff = (kt % H_STG) * H_STAGE;
#pragma unroll
        for (int ks = 0; ks < 2; ks++) {
            uint32_t koff = soff + ks * 32;
            uint32_t a[2][4];
            ldsm4(a[0], aAddr + koff);
            ldsm4(a[1], aAddr + koff + 16 * HROWB);
            uint32_t b[4][4];
#pragma unroll
            for (int jp = 0; jp < 4; jp++)
                ldsm4(b[jp], bAddr + koff + jp * (16 * HROWB));
#pragma unroll
            for (int im = 0; im < 2; im++)
#pragma unroll
                for (int jn = 0; jn < 8; jn++)
                    mma16h(acc[im][jn], a[im], b[jn >> 1][(jn & 1) * 2], b[jn >> 1][(jn & 1) * 2 + 1]);
        }
    }

    int cg = 2 * (lane & 3);
#pragma unroll
    for (int im = 0; im < 2; im++) {
#pragma unroll
        for (int half = 0; half < 2; half++) {
            int m = m0 + wm + im * 16 + (lane >> 2) + half * 8;
            if (m >= cnt) continue;
            if (ep_mode == 3) {
                int tr = c_idx[m]; float wv = c_w[m];
                float* cp = Cf + (size_t)tr * args.ldc + n0 + wn + cg;
#pragma unroll
                for (int jn = 0; jn < 8; jn++) {
                    atomicAdd(cp + jn * 8,     wv * acc[im][jn][half * 2 + 0]);
                    atomicAdd(cp + jn * 8 + 1, wv * acc[im][jn][half * 2 + 1]);
                }
            } else if (ep_mode == 1) {
                __half* cp = Ch + (size_t)m * args.ldc + n0 + wn + cg;
#pragma unroll
                for (int jn = 0; jn < 8; jn++)
                    *((__half2*)(cp + jn * 8)) =
                        __floats2half2_rn(acc[im][jn][half * 2 + 0], acc[im][jn][half * 2 + 1]);
            } else if (ep_mode == 2) {
                int bb = m >> 11, ss = m & (S_ - 1);
#pragma unroll
                for (int jn = 0; jn < 8; jn++) {
                    int col = n0 + wn + cg + jn * 8;
                    int hh = col >> 7, d = col & 127;
                    size_t base = ((size_t)(bb * NH_ + hh) * HD_ + d) * S_ + ss;
                    args.H2[base]      = __float2half_rn(acc[im][jn][half * 2 + 0]);
                    args.H2[base + S_] = __float2half_rn(acc[im][jn][half * 2 + 1]);
                }
            } else {
                float* cp = Cf + (size_t)m * args.ldc + n0 + wn + cg;
                if (args.resid) {
                    const float* rp = args.resid + (size_t)m * args.ldc + n0 + wn + cg;
#pragma unroll
                    for (int jn = 0; jn < 8; jn++) {
                        float2 r = *((const float2*)(rp + jn * 8));
                        float2 o;
                        o.x = acc[im][jn][half * 2 + 0] + r.x;
                        o.y = acc[im][jn][half * 2 + 1] + r.y;
                        *((float2*)(cp + jn * 8)) = o;
                    }
                } else {
#pragma unroll
                    for (int jn = 0; jn < 8; jn++) {
                        float2 o;
                        o.x = acc[im][jn][half * 2 + 0];
                        o.y = acc[im][jn][half * 2 + 1];
                        *((float2*)(cp + jn * 8)) = o;
                    }
                }
            }
        }
    }
}

// ==================== fused gate+up+SwiGLU GEMM ====================
// z = expert. hg16[e][slot][col] = silu(x·Wg^T) * (x·Wu^T), fp32 accum, A frags shared.
__global__ void __launch_bounds__(256, 1)
hgemm_gateup(const GArgs args) {
    int e = blockIdx.z;
    const __half* Bg = args.B0 + (size_t)e * args.bStride;
    const __half* Bu = args.B1 + (size_t)e * args.bStride;
    __half* Ch = args.H0 + (size_t)e * args.cStride;
    const int* a_idx = args.tok + e * T_;
    int cnt = args.cntp[e];

    int m0 = blockIdx.y * 128, n0 = blockIdx.x * 128;
    if (m0 >= cnt) return;

    extern __shared__ char smem[];
    uint32_t sA  = smem_u32(smem);
    uint32_t sBg = sA + H_STG * H_STAGE;
    uint32_t sBu = sBg + H_STG * H_STAGE;

    int tid = threadIdx.x;
    int lane = tid & 31, w = tid >> 5;
    int wm = (w & 3) * 32, wn = (w >> 2) * 64;

    int lrow = tid >> 2, lch = tid & 3;
    const __half* gA[2]; const __half* gBg[2]; const __half* gBu[2];
    uint32_t stA[2], stBg[2], stBu[2];
#pragma unroll
    for (int rr = 0; rr < 2; rr++) {
        int r = lrow + rr * 64;
        int mr = m0 + r;
        int grow = (mr < cnt) ? a_idx[mr] : 0;
        gA[rr]  = args.A + (size_t)grow * args.lda + lch * 8;
        gBg[rr] = Bg + (size_t)(n0 + r) * args.ldb + lch * 8;
        gBu[rr] = Bu + (size_t)(n0 + r) * args.ldb + lch * 8;
        stA[rr]  = sA  + r * HROWB + lch * 16;
        stBg[rr] = sBg + r * HROWB + lch * 16;
        stBu[rr] = sBu + r * HROWB + lch * 16;
    }

    uint32_t aAddr  = sA  + (wm + (lane & 15)) * HROWB + ((lane >> 4) & 1) * 16;
    uint32_t bgAddr = sBg + (wn + (lane & 7) + 8 * ((lane >> 4) & 1)) * HROWB
                          + ((lane >> 3) & 1) * 16;
    uint32_t buAddr = sBu + (wn + (lane & 7) + 8 * ((lane >> 4) & 1)) * HROWB
                          + ((lane >> 3) & 1) * 16;

    float accg[2][8][4], accu[2][8][4];
#pragma unroll
    for (int i = 0; i < 2; i++)
#pragma unroll
        for (int j = 0; j < 8; j++)
#pragma unroll
            for (int q = 0; q < 4; q++) { accg[i][j][q] = 0.f; accu[i][j][q] = 0.f; }

    int nk = args.K / 32;

#pragma unroll
    for (int s = 0; s < 2; s++) {
#pragma unroll
        for (int rr = 0; rr < 2; rr++) {
            cpa16(stA[rr]  + s * H_STAGE, gA[rr]  + s * 32);
            cpa16(stBg[rr] + s * H_STAGE, gBg[rr] + s * 32);
            cpa16(stBu[rr] + s * H_STAGE, gBu[rr] + s * 32);
        }
        cpa_commit();
    }

    for (int kt = 0; kt < nk; kt++) {
        cpa_wait1();
        __syncthreads();
        if (kt + 2 < nk) {
            int kb = (kt + 2) * 32;
            uint32_t off = ((kt + 2) % H_STG) * H_STAGE;
#pragma unroll
            for (int rr = 0; rr < 2; rr++) {
                cpa16(stA[rr]  + off, gA[rr]  + kb);
                cpa16(stBg[rr] + off, gBg[rr] + kb);
                cpa16(stBu[rr] + off, gBu[rr] + kb);
            }
        }
        cpa_commit();

        uint32_t soff = (kt % H_STG) * H_STAGE;
#pragma unroll
        for (int ks = 0; ks < 2; ks++) {
            uint32_t koff = soff + ks * 32;
            uint32_t a[2][4];
            ldsm4(a[0], aAddr + koff);
            ldsm4(a[1], aAddr + koff + 16 * HROWB);
            uint32_t bg[4][4];
#pragma unroll
            for (int jp = 0; jp < 4; jp++)
                ldsm4(bg[jp], bgAddr + koff + jp * (16 * HROWB));
#pragma unroll
            for (int im = 0; im < 2; im++)
#pragma unroll
                for (int jn = 0; jn < 8; jn++)
                    mma16h(accg[im][jn], a[im], bg[jn >> 1][(jn & 1) * 2], bg[jn >> 1][(jn & 1) * 2 + 1]);
            uint32_t bu[4][4];
#pragma unroll
            for (int jp = 0; jp < 4; jp++)
                ldsm4(bu[jp], buAddr + koff + jp * (16 * HROWB));
#pragma unroll
            for (int im = 0; im < 2; im++)
#pragma unroll
                for (int jn = 0; jn < 8; jn++)
                    mma16h(accu[im][jn], a[im], bu[jn >> 1][(jn & 1) * 2], bu[jn >> 1][(jn & 1) * 2 + 1]);
        }
    }

    int cg = 2 * (lane & 3);
#pragma unroll
    for (int im = 0; im < 2; im++) {
#pragma unroll
        for (int half = 0; half < 2; half++) {
            int m = m0 + wm + im * 16 + (lane >> 2) + half * 8;
            if (m >= cnt) continue;
            __half* cp = Ch + (size_t)m * args.ldc + n0 + wn + cg;
#pragma unroll
            for (int jn = 0; jn < 8; jn++) {
                float g0 = accg[im][jn][half * 2 + 0], u0 = accu[im][jn][half * 2 + 0];
                float g1 = accg[im][jn][half * 2 + 1], u1 = accu[im][jn][half * 2 + 1];
                float r0 = g0 / (1.f + __expf(-g0)) * u0;
                float r1 = g1 / (1.f + __expf(-g1)) * u1;
                *((__half2*)(cp + jn * 8)) = __floats2half2_rn(r0, r1);
            }
        }
    }
}

// ==================== causal scores (fp16 pipelined) ====================
__global__ void __launch_bounds__(256, 2)
attn_score_h(const __half* __restrict__ Q, const __half* __restrict__ K16) {
    int bh = blockIdx.z, b = bh >> 4, h = bh & 15;
    int m0 = blockIdx.y * 128, n0 = blockIdx.x * 128;
    if (n0 > m0) return;

    const __half* Qb = Q + (size_t)b * S_ * H_ + h * HD_;
    const __half* Kb = K16 + (size_t)b * S_ * H_ + h * HD_;
    float* Sb = g_att + (size_t)bh * S_ * S_;

    extern __shared__ char smem[];
    uint32_t sA = smem_u32(smem);
    uint32_t sB = sA + H_STG * H_STAGE;

    int tid = threadIdx.x;
    int lane = tid & 31, w = tid >> 5;
    int wm = (w & 3) * 32, wn = (w >> 2) * 64;

    int lrow = tid >> 2, lch = tid & 3;
    const __half* gA[2]; const __half* gB[2];
    uint32_t stA[2], stB[2];
#pragma unroll
    for (int rr = 0; rr < 2; rr++) {
        int r = lrow + rr * 64;
        gA[rr] = Qb + (size_t)(m0 + r) * H_ + lch * 8;
        gB[rr] = Kb + (size_t)(n0 + r) * H_ + lch * 8;
        stA[rr] = sA + r * HROWB + lch * 16;
        stB[rr] = sB + r * HROWB + lch * 16;
    }

    uint32_t aAddr = sA + (wm + (lane & 15)) * HROWB + ((lane >> 4) & 1) * 16;
    uint32_t bAddr = sB + (wn + (lane & 7) + 8 * ((lane >> 4) & 1)) * HROWB
                        + ((lane >> 3) & 1) * 16;

    float acc[2][8][4];
#pragma unroll
    for (int i = 0; i < 2; i++)
#pragma unroll
        for (int j = 0; j < 8; j++)
#pragma unroll
            for (int q = 0; q < 4; q++) acc[i][j][q] = 0.f;

    const int nk = HD_ / 32;

#pragma unroll
    for (int s = 0; s < 2; s++) {
#pragma unroll
        for (int rr = 0; rr < 2; rr++) {
            cpa16(stA[rr] + s * H_STAGE, gA[rr] + s * 32);
            cpa16(stB[rr] + s * H_STAGE, gB[rr] + s * 32);
        }
        cpa_commit();
    }

    for (int kt = 0; kt < nk; kt++) {
        cpa_wait1();
        __syncthreads();
        if (kt + 2 < nk) {
            int kb = (kt + 2) * 32;
            uint32_t off = ((kt + 2) % H_STG) * H_STAGE;
#pragma unroll
            for (int rr = 0; rr < 2; rr++) {
                cpa16(stA[rr] + off, gA[rr] + kb);
                cpa16(stB[rr] + off, gB[rr] + kb);
            }
        }
        cpa_commit();

        uint32_t soff = (kt % H_STG) * H_STAGE;
#pragma unroll
        for (int ks = 0; ks < 2; ks++) {
            uint32_t koff = soff + ks * 32;
            uint32_t a[2][4];
            ldsm4(a[0], aAddr + koff);
            ldsm4(a[1], aAddr + koff + 16 * HROWB);
            uint32_t b2[4][4];
#pragma unroll
            for (int jp = 0; jp < 4; jp++)
                ldsm4(b2[jp], bAddr + koff + jp * (16 * HROWB));
#pragma unroll
            for (int im = 0; im < 2; im++)
#pragma unroll
                for (int jn = 0; jn < 8; jn++)
                    mma16h(acc[im][jn], a[im], b2[jn >> 1][(jn & 1) * 2], b2[jn >> 1][(jn & 1) * 2 + 1]);
        }
    }

    int cg = 2 * (lane & 3);
#pragma unroll
    for (int im = 0; im < 2; im++) {
#pragma unroll
        for (int half = 0; half < 2; half++) {
            int i = m0 + wm + im * 16 + (lane >> 2) + half * 8;
            float* cp = Sb + (size_t)i * S_ + n0 + wn + cg;
#pragma unroll
            for (int jn = 0; jn < 8; jn++) {
                int j = n0 + wn + cg + jn * 8;
                float2 o;
                o.x = (j     > i) ? -1e30f : acc[im][jn][half * 2 + 0] * ATT_SCALE;
                o.y = (j + 1 > i) ? -1e30f : acc[im][jn][half * 2 + 1] * ATT_SCALE;
                *((float2*)(cp + jn * 8)) = o;
            }
        }
    }
}

// ==================== adaptive row softmax: fp32 scores in, fp16 P out ====================
__global__ void softmax_k(__half* __restrict__ P) {
    int r = blockIdx.x & (S_ - 1);
    const float* row = g_att + (size_t)blockIdx.x * S_;
    __half* prow = P + (size_t)blockIdx.x * S_;
    int len = r + 1;
    int tid = threadIdx.x;
    float v[8];
    float mx = -1e30f;
#pragma unroll
    for (int i = 0; i < 8; i++) {
        int j = tid + i * 256;
        v[i] = (j < len) ? row[j] : -1e30f;
        mx = fmaxf(mx, v[i]);
    }
    __shared__ float red[32];
    for (int off = 16; off; off >>= 1) mx = fmaxf(mx, __shfl_xor_sync(0xffffffffu, mx, off));
    if ((tid & 31) == 0) red[tid >> 5] = mx;
    __syncthreads();
    if (tid < 32) {
        float m2 = (tid < 8) ? red[tid] : -1e38f;
        for (int off = 16; off; off >>= 1) m2 = fmaxf(m2, __shfl_xor_sync(0xffffffffu, m2, off));
        if (tid == 0) red[0] = m2;
    }
    __syncthreads();
    mx = red[0];
    float s = 0.f;
#pragma unroll
    for (int i = 0; i < 8; i++) { v[i] = __expf(v[i] - mx); s += v[i]; }
    __syncthreads();
    for (int off = 16; off; off >>= 1) s += __shfl_xor_sync(0xffffffffu, s, off);
    if ((tid & 31) == 0) red[tid >> 5] = s;
    __syncthreads();
    if (tid < 32) {
        float s2 = (tid < 8) ? red[tid] : 0.f;
        for (int off = 16; off; off >>= 1) s2 += __shfl_xor_sync(0xffffffffu, s2, off);
        if (tid == 0) red[0] = s2;
    }
    __syncthreads();
    float inv = 1.f / red[0];
#pragma unroll
    for (int i = 0; i < 8; i++) {
        int j = tid + i * 256;
        if (j < len) prow[j] = __float2half_rn(v[i] * inv);
    }
    int kmax = ((r >> 7) + 1) << 7;
    for (int j = len + tid; j < kmax; j += 256) prow[j] = __float2half_rn(0.f);
}

// ==================== P @ Vt (fp16 pipelined, causal-truncated) ====================
__global__ void __launch_bounds__(256, 2)
attn_pv_h(const __half* __restrict__ P, const __half* __restrict__ Vt,
          __half* __restrict__ O) {
    int bh = blockIdx.y, b = bh >> 4, h = bh & 15;
    int m0 = blockIdx.x * 128;
    const __half* Pb = P + (size_t)bh * S_ * S_;
    const __half* Vb = Vt + (size_t)bh * HD_ * S_;

    extern __shared__ char smem[];
    uint32_t sA = smem_u32(smem);
    uint32_t sB = sA + H_STG * H_STAGE;

    int tid = threadIdx.x;
    int lane = tid & 31, w = tid >> 5;
    int wm = (w & 3) * 32, wn = (w >> 2) * 64;

    int lrow = tid >> 2, lch = tid & 3;
    const __half* gA[2]; const __half* gB[2];
    uint32_t stA[2], stB[2];
#pragma unroll
    for (int rr = 0; rr < 2; rr++) {
        int r = lrow + rr * 64;
        gA[rr] = Pb + (size_t)(m0 + r) * S_ + lch * 8;
        gB[rr] = Vb + (size_t)r * S_ + lch * 8;
        stA[rr] = sA + r * HROWB + lch * 16;
        stB[rr] = sB + r * HROWB + lch * 16;
    }

    uint32_t aAddr = sA + (wm + (lane & 15)) * HROWB + ((lane >> 4) & 1) * 16;
    uint32_t bAddr = sB + (wn + (lane & 7) + 8 * ((lane >> 4) & 1)) * HROWB
                        + ((lane >> 3) & 1) * 16;

    float acc[2][8][4];
#pragma unroll
    for (int i = 0; i < 2; i++)
#pragma unroll
        for (int j = 0; j < 8; j++)
#pragma unroll
            for (int q = 0; q < 4; q++) acc[i][j][q] = 0.f;

    int nk = (m0 + 128) / 32;

#pragma unroll
    for (int s = 0; s < 2; s++) {
#pragma unroll
        for (int rr = 0; rr < 2; rr++) {
            cpa16(stA[rr] + s * H_STAGE, gA[rr] + s * 32);
            cpa16(stB[rr] + s * H_STAGE, gB[rr] + s * 32);
        }
        cpa_commit();
    }

    for (int kt = 0; kt < nk; kt++) {
        cpa_wait1();
        __syncthreads();
        if (kt + 2 < nk) {
            int kb = (kt + 2) * 32;
            uint32_t off = ((kt + 2) % H_STG) * H_STAGE;
#pragma unroll
            for (int rr = 0; rr < 2; rr++) {
                cpa16(stA[rr] + off, gA[rr] + kb);
                cpa16(stB[rr] + off, gB[rr] + kb);
            }
        }
        cpa_commit();

        uint32_t soff = (kt % H_STG) * H_STAGE;
#pragma unroll
        for (int ks = 0; ks < 2; ks++) {
            uint32_t koff = soff + ks * 32;
            uint32_t a[2][4];
            ldsm4(a[0], aAddr + koff);
            ldsm4(a[1], aAddr + koff + 16 * HROWB);
            uint32_t b2[4][4];
#pragma unroll
            for (int jp = 0; jp < 4; jp++)
                ldsm4(b2[jp], bAddr + koff + jp * (16 * HROWB));
#pragma unroll
            for (int im = 0; im < 2; im++)
#pragma unroll
                for (int jn = 0; jn < 8; jn++)
                    mma16h(acc[im][jn], a[im], b2[jn >> 1][(jn & 1) * 2], b2[jn >> 1][(jn & 1) * 2 + 1]);
        }
    }

    int cg = 2 * (lane & 3);
#pragma unroll
    for (int im = 0; im < 2; im++) {
#pragma unroll
        for (int half = 0; half < 2; half++) {
            int m = m0 + wm + im * 16 + (lane >> 2) + half * 8;
            __half* cp = O + (size_t)(b * S_ + m) * H_ + h * HD_ + wn + cg;
#pragma unroll
            for (int jn = 0; jn < 8; jn++)
                *((__half2*)(cp + jn * 8)) =
                    __floats2half2_rn(acc[im][jn][half * 2 + 0], acc[im][jn][half * 2 + 1]);
        }
    }
}

// ==================== router (EXACT fp32 input) ====================
__global__ void router_k(const float* __restrict__ xn2e, const float* __restrict__ Wr) {
    int t = blockIdx.x * (blockDim.x >> 5) + (threadIdx.x >> 5);
    if (t >= T_) return;
    int lane = threadIdx.x & 31;
    const float* xr = xn2e + (size_t)t * H_;
    float s[NE_];
#pragma unroll
    for (int e = 0; e < NE_; e++) s[e] = 0.f;
    for (int j = lane; j < H_; j += 32) {
        float xv = xr[j];
#pragma unroll
        for (int e = 0; e < NE_; e++) s[e] += xv * Wr[e * H_ + j];
    }
#pragma unroll
    for (int e = 0; e < NE_; e++)
        for (int off = 16; off; off >>= 1) s[e] += __shfl_xor_sync(0xffffffffu, s[e], off);
    if (lane == 0) {
        int b0 = 0;
#pragma unroll
        for (int e = 1; e < NE_; e++) if (s[e] > s[b0]) b0 = e;
        int b1 = -1;
#pragma unroll
        for (int e = 0; e < NE_; e++) {
            if (e == b0) continue;
            if (b1 < 0 || s[e] > s[b1]) b1 = e;
        }
        float m = s[b0];
        float e0 = __expf(s[b0] - m), e1 = __expf(s[b1] - m);
        float inv = 1.f / (e0 + e1);
        int pos = atomicAdd(&g_cnt[b0], 1);
        g_tok[b0 * T_ + pos] = t; g_wt[b0 * T_ + pos] = e0 * inv;
        pos = atomicAdd(&g_cnt[b1], 1);
        g_tok[b1 * T_ + pos] = t; g_wt[b1 * T_ + pos] = e1 * inv;
    }
}

// ==================== host ====================
extern "C" void kernel_launch(void* const* d_in, const int* in_sizes, int n_in,
                              void* d_out, int out_size) {
    const float* x    = (const float*)d_in[0];
    const float* Wq   = (const float*)d_in[1];
    const float* Wk   = (const float*)d_in[2];
    const float* Wv   = (const float*)d_in[3];
    const float* Wo   = (const float*)d_in[4];
    const float* wln1 = (const float*)d_in[5];
    const float* wln2 = (const float*)d_in[6];
    const float* Wr   = (const float*)d_in[7];
    const float* Wg   = (const float*)d_in[8];
    const float* Wu   = (const float*)d_in[9];
    const float* Wd   = (const float*)d_in[10];
    float* out = (float*)d_out;

    float *p_hg, *p_rex, *p_wt;
    __half *p_q16, *p_k16, *p_vt16, *p_xn16, *p_ao16, *p_xn216, *p_hg16, *p_w16;
    int *p_tok, *p_cnt;
    cudaGetSymbolAddress((void**)&p_hg,    g_hg);
    cudaGetSymbolAddress((void**)&p_rex,   g_rex);
    cudaGetSymbolAddress((void**)&p_q16,   g_q16);
    cudaGetSymbolAddress((void**)&p_k16,   g_k16);
    cudaGetSymbolAddress((void**)&p_vt16,  g_vt16);
    cudaGetSymbolAddress((void**)&p_xn16,  g_xn16);
    cudaGetSymbolAddress((void**)&p_ao16,  g_ao16);
    cudaGetSymbolAddress((void**)&p_xn216, g_xn216);
    cudaGetSymbolAddress((void**)&p_hg16,  g_hg16);
    cudaGetSymbolAddress((void**)&p_w16,   g_w16);
    cudaGetSymbolAddress((void**)&p_tok,   g_tok);
    cudaGetSymbolAddress((void**)&p_wt,    g_wt);
    cudaGetSymbolAddress((void**)&p_cnt,   g_cnt);

    __half* p_P = (__half*)p_hg;

    static int inited = 0;
    static cudaStream_t s2;
    static cudaEvent_t ev_fork, ev_wo, ev_moe;
    if (!inited) {
        cudaFuncSetAttribute(hgemm, cudaFuncAttributeMaxDynamicSharedMemorySize, H_SMEM);
        cudaFuncSetAttribute(hgemm_gateup, cudaFuncAttributeMaxDynamicSharedMemorySize, GU_SMEM);
        cudaFuncSetAttribute(attn_score_h, cudaFuncAttributeMaxDynamicSharedMemorySize, H_SMEM);
        cudaFuncSetAttribute(attn_pv_h, cudaFuncAttributeMaxDynamicSharedMemorySize, H_SMEM);
        int pLeast, pGreatest;
        cudaDeviceGetStreamPriorityRange(&pLeast, &pGreatest);
        cudaStreamCreateWithPriority(&s2, cudaStreamNonBlocking, pLeast);
        cudaEventCreateWithFlags(&ev_fork, cudaEventDisableTiming);
        cudaEventCreateWithFlags(&ev_wo,   cudaEventDisableTiming);
        cudaEventCreateWithFlags(&ev_moe,  cudaEventDisableTiming);
        inited = 1;
    }

    zero_cnt_k<<<1, 32>>>();

    // main stream: weights needed first
    cvt16_k<<<1024, 256>>>(Wq, p_w16 + OFF_WQ, (size_t)H_ * H_ / 8);
    cvt16_k<<<1024, 256>>>(Wk, p_w16 + OFF_WK, (size_t)H_ * H_ / 8);
    cvt16_k<<<1024, 256>>>(Wv, p_w16 + OFF_WV, (size_t)H_ * H_ / 8);

    // fork: remaining weight conversions overlap with attention phase (low priority)
    cudaEventRecord(ev_fork, 0);
    cudaStreamWaitEvent(s2, ev_fork, 0);
    cvt16_k<<<1024, 256, 0, s2>>>(Wo, p_w16 + OFF_WO, (size_t)H_ * H_ / 8);
    cudaEventRecord(ev_wo, s2);
    cvt16_k<<<4096, 256, 0, s2>>>(Wg, p_w16 + OFF_WG, (size_t)NE_ * I_ * H_ / 8);
    cvt16_k<<<4096, 256, 0, s2>>>(Wu, p_w16 + OFF_WU, (size_t)NE_ * I_ * H_ / 8);
    cvt16_k<<<4096, 256, 0, s2>>>(Wd, p_w16 + OFF_WD, (size_t)NE_ * H_ * I_ / 8);
    cudaEventRecord(ev_moe, s2);

    rmsnorm_k<<<T_, 256>>>(x, wln1, p_xn16, nullptr);

    // QKV fused: q,k -> fp16 [t][H]; v -> fp16 transposed [b,h][d][s]
    {
        GArgs a = {};
        a.A = p_xn16;
        a.B0 = p_w16 + OFF_WQ; a.B1 = p_w16 + OFF_WK; a.B2 = p_w16 + OFF_WV;
        a.H0 = p_q16; a.H1 = p_k16; a.H2 = p_vt16;
        a.M = T_; a.N = H_; a.K = H_; a.lda = H_; a.ldb = H_; a.ldc = H_;
        a.mode = 0; a.qkv = 1;
        hgemm<<<dim3(H_ / 128, T_ / 128, 3), 256, H_SMEM>>>(a);
    }

    attn_score_h<<<dim3(S_ / 128, S_ / 128, B_ * NH_), 256, H_SMEM>>>(p_q16, p_k16);
    softmax_k<<<B_ * NH_ * S_, 256>>>(p_P);
    attn_pv_h<<<dim3(S_ / 128, B_ * NH_), 256, H_SMEM>>>(p_P, p_vt16, p_ao16);

    // join: Wo fp16 ready
    cudaStreamWaitEvent(0, ev_wo, 0);

    // Wo projection + fused residual (fp32 out)
    {
        GArgs a = {};
        a.A = p_ao16; a.B0 = p_w16 + OFF_WO; a.C0 = out;
        a.resid = x;
        a.M = T_; a.N = H_; a.K = H_; a.lda = H_; a.ldb = H_; a.ldc = H_;
        a.mode = 0;
        hgemm<<<dim3(H_ / 128, T_ / 128, 1), 256, H_SMEM>>>(a);
    }

    rmsnorm_k<<<T_, 256>>>(out, wln2, p_xn216, p_rex);
    router_k<<<T_ / 8, 256>>>(p_rex, Wr);

    // join: MoE weights fp16 ready
    cudaStreamWaitEvent(0, ev_moe, 0);

    // MoE fused gate+up+SwiGLU (gathered A, fp32-accum silu, fp16 out)
    {
        GArgs a = {};
        a.A = p_xn216;
        a.B0 = p_w16 + OFF_WG; a.B1 = p_w16 + OFF_WU;
        a.H0 = p_hg16;
        a.M = T_; a.N = I_; a.K = H_; a.lda = H_; a.ldb = H_; a.ldc = I_;
        a.tok = p_tok; a.cntp = p_cnt;
        a.bStride = (size_t)I_ * H_; a.cStride = (size_t)T_ * I_;
        hgemm_gateup<<<dim3(I_ / 128, T_ / 128, NE_), 256, GU_SMEM>>>(a);
    }

    // MoE down: atomic scatter-add into out
    {
        GArgs a = {};
        a.A = p_hg16; a.B0 = p_w16 + OFF_WD; a.C0 = out;
        a.M = T_; a.N = H_; a.K = I_; a.lda = I_; a.ldb = I_; a.ldc = H_;
        a.tok = p_tok; a.wt = p_wt; a.cntp = p_cnt;
        a.aStride = (size_t)T_ * I_; a.bStride = (size_t)H_ * I_;
        a.mode = 2;
        hgemm<<<dim3(H_ / 128, T_ / 128, NE_), 256, H_SMEM>>>(a);
    }
}

// round 14
// speedup vs baseline: 1.0576x; 1.0576x over previous
#include <cuda_runtime.h>
#include <cuda_fp16.h>
#include <math.h>
#include <stdint.h>

#define B_   2
#define S_   2048
#define H_   2048
#define NH_  16
#define HD_  128
#define NE_  8
#define I_   4096
#define T_   (B_*S_)
#define EPS_ 1e-5f
#define ATT_SCALE 0.08838834764831845f

// -------------------- scratch --------------------
__device__ float  g_att[(size_t)B_*NH_*S_*S_];     // fp32 scores
__device__ float  g_hg [(size_t)NE_*T_*I_];        // aliased: P(half); gate/up pre-act (2x half)
__device__ float  g_rex[(size_t)T_*H_];            // ln2 exact (router)
__device__ __half g_q16  [(size_t)T_*H_];
__device__ __half g_k16  [(size_t)T_*H_];
__device__ __half g_vt16 [(size_t)B_*NH_*HD_*S_];  // V transposed: [b,h][d][s]
__device__ __half g_xn16 [(size_t)T_*H_];
__device__ __half g_ao16 [(size_t)T_*H_];
__device__ __half g_xn216[(size_t)T_*H_];
__device__ __half g_hg16 [(size_t)NE_*T_*I_];      // swiglu out (down A)
#define OFF_WQ ((size_t)0)
#define OFF_WK ((size_t)H_*H_)
#define OFF_WV ((size_t)2*H_*H_)
#define OFF_WO ((size_t)3*H_*H_)
#define OFF_WG ((size_t)4*H_*H_)
#define OFF_WU (OFF_WG + (size_t)NE_*I_*H_)
#define OFF_WD (OFF_WU + (size_t)NE_*I_*H_)
#define W16_TOTAL (OFF_WD + (size_t)NE_*H_*I_)
__device__ __half g_w16[W16_TOTAL];
__device__ int   g_tok[NE_*T_];
__device__ float g_wt [NE_*T_];
__device__ int   g_cnt[NE_];

// -------------------- helpers --------------------
__device__ __forceinline__ void mma16h(float* c, const uint32_t* a, uint32_t b0, uint32_t b1) {
    asm volatile("mma.sync.aligned.m16n8k16.row.col.f32.f16.f16.f32 "
        "{%0,%1,%2,%3},{%4,%5,%6,%7},{%8,%9},{%0,%1,%2,%3};"
        : "+f"(c[0]), "+f"(c[1]), "+f"(c[2]), "+f"(c[3])
        : "r"(a[0]), "r"(a[1]), "r"(a[2]), "r"(a[3]), "r"(b0), "r"(b1));
}
__device__ __forceinline__ void ldsm4(uint32_t* r, uint32_t addr) {
    asm volatile("ldmatrix.sync.aligned.m8n8.x4.shared.b16 {%0,%1,%2,%3},[%4];"
        : "=r"(r[0]), "=r"(r[1]), "=r"(r[2]), "=r"(r[3]) : "r"(addr));
}
__device__ __forceinline__ void cpa16(uint32_t dst, const void* src) {
    asm volatile("cp.async.cg.shared.global [%0], [%1], 16;" :: "r"(dst), "l"(src));
}
__device__ __forceinline__ void cpa_commit() { asm volatile("cp.async.commit_group;"); }
__device__ __forceinline__ void cpa_wait1()  { asm volatile("cp.async.wait_group 1;" ::: "memory"); }
__device__ __forceinline__ uint32_t smem_u32(const void* p) {
    uint32_t a; asm("{ .reg .u64 t; cvta.to.shared.u64 t, %1; cvt.u32.u64 %0, t; }"
                    : "=r"(a) : "l"(p));
    return a;
}

#define HROWB 80
#define H_STG 3
#define H_STAGE (128*HROWB)
#define H_SMEM (2*H_STG*H_STAGE)      // 61440 B

// -------------------- small kernels --------------------
__global__ void zero_cnt_k() { if (threadIdx.x < NE_) g_cnt[threadIdx.x] = 0; }

__global__ void cvt16_k(const float* __restrict__ s, __half* __restrict__ d, size_t n8) {
    size_t stride = (size_t)gridDim.x * blockDim.x;
    const float4* S = (const float4*)s;
    uint4* D = (uint4*)d;
    for (size_t i = (size_t)blockIdx.x * blockDim.x + threadIdx.x; i < n8; i += stride) {
        float4 v0 = S[2 * i], v1 = S[2 * i + 1];
        __half2 h0 = __floats2half2_rn(v0.x, v0.y);
        __half2 h1 = __floats2half2_rn(v0.z, v0.w);
        __half2 h2 = __floats2half2_rn(v1.x, v1.y);
        __half2 h3 = __floats2half2_rn(v1.z, v1.w);
        uint4 o;
        o.x = *(const uint32_t*)&h0;
        o.y = *(const uint32_t*)&h1;
        o.z = *(const uint32_t*)&h2;
        o.w = *(const uint32_t*)&h3;
        D[i] = o;
    }
}

__global__ void rmsnorm_k(const float* __restrict__ x, const float* __restrict__ w,
                          __half* __restrict__ o16, float* __restrict__ o_exact) {
    int t = blockIdx.x;
    const float* xr = x + (size_t)t * H_;
    float s = 0.f;
    for (int j = threadIdx.x; j < H_; j += blockDim.x) { float v = xr[j]; s += v * v; }
    __shared__ float red[32];
    for (int off = 16; off; off >>= 1) s += __shfl_xor_sync(0xffffffffu, s, off);
    if ((threadIdx.x & 31) == 0) red[threadIdx.x >> 5] = s;
    __syncthreads();
    if (threadIdx.x < 32) {
        float v = (threadIdx.x < (blockDim.x >> 5)) ? red[threadIdx.x] : 0.f;
        for (int off = 16; off; off >>= 1) v += __shfl_xor_sync(0xffffffffu, v, off);
        if (threadIdx.x == 0) red[0] = v;
    }
    __syncthreads();
    float inv = rsqrtf(red[0] / (float)H_ + EPS_);
    __half* orow = o16 + (size_t)t * H_;
    if (o_exact) {
        float* erow = o_exact + (size_t)t * H_;
        for (int j = threadIdx.x; j < H_; j += blockDim.x) {
            float v = xr[j] * inv * w[j];
            erow[j] = v;
            orow[j] = __float2half_rn(v);
        }
    } else {
        for (int j = threadIdx.x; j < H_; j += blockDim.x)
            orow[j] = __float2half_rn(xr[j] * inv * w[j]);
    }
}

// swiglu: fp16 pre-acts in, fp16 out
__global__ void swiglu_all_k(const __half* __restrict__ hgp, const __half* __restrict__ hup,
                             __half* __restrict__ ho) {
    int e = blockIdx.y;
    int cnt = g_cnt[e];
    const __half2* G = (const __half2*)(hgp + (size_t)e * T_ * I_);
    const __half2* U = (const __half2*)(hup + (size_t)e * T_ * I_);
    __half2* O = (__half2*)(ho + (size_t)e * T_ * I_);
    size_t total = (size_t)cnt * (I_ / 2);
    size_t stride = (size_t)gridDim.x * blockDim.x;
    for (size_t i = (size_t)blockIdx.x * blockDim.x + threadIdx.x; i < total; i += stride) {
        float2 g = __half22float2(G[i]);
        float2 u = __half22float2(U[i]);
        float a = g.x / (1.f + __expf(-g.x)) * u.x;
        float b = g.y / (1.f + __expf(-g.y)) * u.y;
        O[i] = __floats2half2_rn(a, b);
    }
}

// ==================== fp16 MMA GEMM ====================
struct GArgs {
    const __half* A;
    const __half* B0; const __half* B1; const __half* B2;
    float* C0;
    __half* H0; __half* H1; __half* H2;
    const float* resid;
    int M, N, K, lda, ldb, ldc;
    const int* tok; const float* wt; const int* cntp;
    size_t aStride, bStride, cStride;
    int mode;
    int qkv;
};

__global__ void __launch_bounds__(256, 2)
hgemm(const GArgs args) {
    int z = blockIdx.z;
    const __half* A = args.A;
    const __half* B;
    const int* a_idx = nullptr; const int* c_idx = nullptr; const float* c_w = nullptr;
    int cnt = args.M;
    int ep_mode;          // 0=fp32 (resid opt), 1=half H, 2=vtrans, 3=atomic
    float* Cf = args.C0;
    __half* Ch = nullptr;

    if (args.mode == 0) {
        B = (z == 0) ? args.B0 : (z == 1 ? args.B1 : args.B2);
        if (args.qkv) {
            if (z < 2) { Ch = z ? args.H1 : args.H0; ep_mode = 1; }
            else ep_mode = 2;
        } else ep_mode = 0;
    } else if (args.mode == 1) {
        int e = z >> 1;
        B = ((z & 1) ? args.B1 : args.B0) + (size_t)e * args.bStride;
        Ch = ((z & 1) ? args.H1 : args.H0) + (size_t)e * args.cStride;
        a_idx = args.tok + e * T_;
        cnt = args.cntp[e];
        ep_mode = 1;
    } else {
        int e = z;
        A = args.A + (size_t)e * args.aStride;
        B = args.B0 + (size_t)e * args.bStride;
        c_idx = args.tok + e * T_;
        c_w = args.wt + e * T_;
        cnt = args.cntp[e];
        ep_mode = 3;
    }

    int m0 = blockIdx.y * 128, n0 = blockIdx.x * 128;
    if (m0 >= cnt) return;

    extern __shared__ char smem[];
    uint32_t sA = smem_u32(smem);
    uint32_t sB = sA + H_STG * H_STAGE;

    int tid = threadIdx.x;
    int lane = tid & 31, w = tid >> 5;
    int wm = (w & 3) * 32, wn = (w >> 2) * 64;

    int lrow = tid >> 2;
    int lch  = tid & 3;
    const __half* gA[2]; const __half* gB[2];
    uint32_t stA[2], stB[2];
#pragma unroll
    for (int rr = 0; rr < 2; rr++) {
        int r = lrow + rr * 64;
        int mr = m0 + r;
        int grow = a_idx ? ((mr < cnt) ? a_idx[mr] : 0) : mr;
        gA[rr] = A + (size_t)grow * args.lda + lch * 8;
        gB[rr] = B + (size_t)(n0 + r) * args.ldb + lch * 8;
        stA[rr] = sA + r * HROWB + lch * 16;
        stB[rr] = sB + r * HROWB + lch * 16;
    }

    uint32_t aAddr = sA + (wm + (lane & 15)) * HROWB + ((lane >> 4) & 1) * 16;
    uint32_t bAddr = sB + (wn + (lane & 7) + 8 * ((lane >> 4) & 1)) * HROWB
                        + ((lane >> 3) & 1) * 16;

    float acc[2][8][4];
#pragma unroll
    for (int i = 0; i < 2; i++)
#pragma unroll
        for (int j = 0; j < 8; j++)
#pragma unroll
            for (int q = 0; q < 4; q++) acc[i][j][q] = 0.f;

    int nk = args.K / 32;

#pragma unroll
    for (int s = 0; s < 2; s++) {
#pragma unroll
        for (int rr = 0; rr < 2; rr++) {
            cpa16(stA[rr] + s * H_STAGE, gA[rr] + s * 32);
            cpa16(stB[rr] + s * H_STAGE, gB[rr] + s * 32);
        }
        cpa_commit();
    }

    for (int kt = 0; kt < nk; kt++) {
        cpa_wait1();
        __syncthreads();
        if (kt + 2 < nk) {
            int kb = (kt + 2) * 32;
            uint32_t off = ((kt + 2) % H_STG) * H_STAGE;
#pragma unroll
            for (int rr = 0; rr < 2; rr++) {
                cpa16(stA[rr] + off, gA[rr] + kb);
                cpa16(stB[rr] + off, gB[rr] + kb);
            }
        }
        cpa_commit();

        uint32_t soff = (kt % H_STG) * H_STAGE;
#pragma unroll
        for (int ks = 0; ks < 2; ks++) {
            uint32_t koff = soff + ks * 32;
            uint32_t a[2][4];
            ldsm4(a[0], aAddr + koff);
            ldsm4(a[1], aAddr + koff + 16 * HROWB);
            uint32_t b[4][4];
#pragma unroll
            for (int jp = 0; jp < 4; jp++)
                ldsm4(b[jp], bAddr + koff + jp * (16 * HROWB));
#pragma unroll
            for (int im = 0; im < 2; im++)
#pragma unroll
                for (int jn = 0; jn < 8; jn++)
                    mma16h(acc[im][jn], a[im], b[jn >> 1][(jn & 1) * 2], b[jn >> 1][(jn & 1) * 2 + 1]);
        }
    }

    int cg = 2 * (lane & 3);
#pragma unroll
    for (int im = 0; im < 2; im++) {
#pragma unroll
        for (int half = 0; half < 2; half++) {
            int m = m0 + wm + im * 16 + (lane >> 2) + half * 8;
            if (m >= cnt) continue;
            if (ep_mode == 3) {
                int tr = c_idx[m]; float wv = c_w[m];
                float* cp = Cf + (size_t)tr * args.ldc + n0 + wn + cg;
#pragma unroll
                for (int jn = 0; jn < 8; jn++) {
                    atomicAdd(cp + jn * 8,     wv * acc[im][jn][half * 2 + 0]);
                    atomicAdd(cp + jn * 8 + 1, wv * acc[im][jn][half * 2 + 1]);
                }
            } else if (ep_mode == 1) {
                __half* cp = Ch + (size_t)m * args.ldc + n0 + wn + cg;
#pragma unroll
                for (int jn = 0; jn < 8; jn++)
                    *((__half2*)(cp + jn * 8)) =
                        __floats2half2_rn(acc[im][jn][half * 2 + 0], acc[im][jn][half * 2 + 1]);
            } else if (ep_mode == 2) {
                int bb = m >> 11, ss = m & (S_ - 1);
#pragma unroll
                for (int jn = 0; jn < 8; jn++) {
                    int col = n0 + wn + cg + jn * 8;
                    int hh = col >> 7, d = col & 127;
                    size_t base = ((size_t)(bb * NH_ + hh) * HD_ + d) * S_ + ss;
                    args.H2[base]      = __float2half_rn(acc[im][jn][half * 2 + 0]);
                    args.H2[base + S_] = __float2half_rn(acc[im][jn][half * 2 + 1]);
                }
            } else {
                float* cp = Cf + (size_t)m * args.ldc + n0 + wn + cg;
                if (args.resid) {
                    const float* rp = args.resid + (size_t)m * args.ldc + n0 + wn + cg;
#pragma unroll
                    for (int jn = 0; jn < 8; jn++) {
                        float2 r = *((const float2*)(rp + jn * 8));
                        float2 o;
                        o.x = acc[im][jn][half * 2 + 0] + r.x;
                        o.y = acc[im][jn][half * 2 + 1] + r.y;
                        *((float2*)(cp + jn * 8)) = o;
                    }
                } else {
#pragma unroll
                    for (int jn = 0; jn < 8; jn++) {
                        float2 o;
                        o.x = acc[im][jn][half * 2 + 0];
                        o.y = acc[im][jn][half * 2 + 1];
                        *((float2*)(cp + jn * 8)) = o;
                    }
                }
            }
        }
    }
}

// ==================== causal scores (fp16 pipelined, triangular grid) ====================
__global__ void __launch_bounds__(256, 2)
attn_score_h(const __half* __restrict__ Q, const __half* __restrict__ K16) {
    int bh = blockIdx.z, b = bh >> 4, h = bh & 15;
    // triangular tile index -> (mt, nt), nt <= mt
    int idx = blockIdx.x;
    int mt = (int)((sqrtf(8.f * idx + 1.f) - 1.f) * 0.5f);
    while ((mt + 1) * (mt + 2) / 2 <= idx) mt++;
    while (mt * (mt + 1) / 2 > idx) mt--;
    int nt = idx - mt * (mt + 1) / 2;
    int m0 = mt * 128, n0 = nt * 128;

    const __half* Qb = Q + (size_t)b * S_ * H_ + h * HD_;
    const __half* Kb = K16 + (size_t)b * S_ * H_ + h * HD_;
    float* Sb = g_att + (size_t)bh * S_ * S_;

    extern __shared__ char smem[];
    uint32_t sA = smem_u32(smem);
    uint32_t sB = sA + H_STG * H_STAGE;

    int tid = threadIdx.x;
    int lane = tid & 31, w = tid >> 5;
    int wm = (w & 3) * 32, wn = (w >> 2) * 64;

    int lrow = tid >> 2, lch = tid & 3;
    const __half* gA[2]; const __half* gB[2];
    uint32_t stA[2], stB[2];
#pragma unroll
    for (int rr = 0; rr < 2; rr++) {
        int r = lrow + rr * 64;
        gA[rr] = Qb + (size_t)(m0 + r) * H_ + lch * 8;
        gB[rr] = Kb + (size_t)(n0 + r) * H_ + lch * 8;
        stA[rr] = sA + r * HROWB + lch * 16;
        stB[rr] = sB + r * HROWB + lch * 16;
    }

    uint32_t aAddr = sA + (wm + (lane & 15)) * HROWB + ((lane >> 4) & 1) * 16;
    uint32_t bAddr = sB + (wn + (lane & 7) + 8 * ((lane >> 4) & 1)) * HROWB
                        + ((lane >> 3) & 1) * 16;

    float acc[2][8][4];
#pragma unroll
    for (int i = 0; i < 2; i++)
#pragma unroll
        for (int j = 0; j < 8; j++)
#pragma unroll
            for (int q = 0; q < 4; q++) acc[i][j][q] = 0.f;

    const int nk = HD_ / 32;

#pragma unroll
    for (int s = 0; s < 2; s++) {
#pragma unroll
        for (int rr = 0; rr < 2; rr++) {
            cpa16(stA[rr] + s * H_STAGE, gA[rr] + s * 32);
            cpa16(stB[rr] + s * H_STAGE, gB[rr] + s * 32);
        }
        cpa_commit();
    }

    for (int kt = 0; kt < nk; kt++) {
        cpa_wait1();
        __syncthreads();
        if (kt + 2 < nk) {
            int kb = (kt + 2) * 32;
            uint32_t off = ((kt + 2) % H_STG) * H_STAGE;
#pragma unroll
            for (int rr = 0; rr < 2; rr++) {
                cpa16(stA[rr] + off, gA[rr] + kb);
                cpa16(stB[rr] + off, gB[rr] + kb);
            }
        }
        cpa_commit();

        uint32_t soff = (kt % H_STG) * H_STAGE;
#pragma unroll
        for (int ks = 0; ks < 2; ks++) {
            uint32_t koff = soff + ks * 32;
            uint32_t a[2][4];
            ldsm4(a[0], aAddr + koff);
            ldsm4(a[1], aAddr + koff + 16 * HROWB);
            uint32_t b2[4][4];
#pragma unroll
            for (int jp = 0; jp < 4; jp++)
                ldsm4(b2[jp], bAddr + koff + jp * (16 * HROWB));
#pragma unroll
            for (int im = 0; im < 2; im++)
#pragma unroll
                for (int jn = 0; jn < 8; jn++)
                    mma16h(acc[im][jn], a[im], b2[jn >> 1][(jn & 1) * 2], b2[jn >> 1][(jn & 1) * 2 + 1]);
        }
    }

    int cg = 2 * (lane & 3);
#pragma unroll
    for (int im = 0; im < 2; im++) {
#pragma unroll
        for (int half = 0; half < 2; half++) {
            int i = m0 + wm + im * 16 + (lane >> 2) + half * 8;
            float* cp = Sb + (size_t)i * S_ + n0 + wn + cg;
#pragma unroll
            for (int jn = 0; jn < 8; jn++) {
                int j = n0 + wn + cg + jn * 8;
                float2 o;
                o.x = (j     > i) ? -1e30f : acc[im][jn][half * 2 + 0] * ATT_SCALE;
                o.y = (j + 1 > i) ? -1e30f : acc[im][jn][half * 2 + 1] * ATT_SCALE;
                *((float2*)(cp + jn * 8)) = o;
            }
        }
    }
}

// ==================== adaptive row softmax: fp32 scores in, fp16 P out ====================
__global__ void softmax_k(__half* __restrict__ P) {
    int r = blockIdx.x & (S_ - 1);
    const float* row = g_att + (size_t)blockIdx.x * S_;
    __half* prow = P + (size_t)blockIdx.x * S_;
    int len = r + 1;
    int tid = threadIdx.x;
    float v[8];
    float mx = -1e30f;
#pragma unroll
    for (int i = 0; i < 8; i++) {
        int j = tid + i * 256;
        v[i] = (j < len) ? row[j] : -1e30f;
        mx = fmaxf(mx, v[i]);
    }
    __shared__ float red[32];
    for (int off = 16; off; off >>= 1) mx = fmaxf(mx, __shfl_xor_sync(0xffffffffu, mx, off));
    if ((tid & 31) == 0) red[tid >> 5] = mx;
    __syncthreads();
    if (tid < 32) {
        float m2 = (tid < 8) ? red[tid] : -1e38f;
        for (int off = 16; off; off >>= 1) m2 = fmaxf(m2, __shfl_xor_sync(0xffffffffu, m2, off));
        if (tid == 0) red[0] = m2;
    }
    __syncthreads();
    mx = red[0];
    float s = 0.f;
#pragma unroll
    for (int i = 0; i < 8; i++) { v[i] = __expf(v[i] - mx); s += v[i]; }
    __syncthreads();
    for (int off = 16; off; off >>= 1) s += __shfl_xor_sync(0xffffffffu, s, off);
    if ((tid & 31) == 0) red[tid >> 5] = s;
    __syncthreads();
    if (tid < 32) {
        float s2 = (tid < 8) ? red[tid] : 0.f;
        for (int off = 16; off; off >>= 1) s2 += __shfl_xor_sync(0xffffffffu, s2, off);
        if (tid == 0) red[0] = s2;
    }
    __syncthreads();
    float inv = 1.f / red[0];
#pragma unroll
    for (int i = 0; i < 8; i++) {
        int j = tid + i * 256;
        if (j < len) prow[j] = __float2half_rn(v[i] * inv);
    }
    int kmax = ((r >> 7) + 1) << 7;
    for (int j = len + tid; j < kmax; j += 256) prow[j] = __float2half_rn(0.f);
}

// ==================== P @ Vt (fp16 pipelined, causal-truncated) ====================
__global__ void __launch_bounds__(256, 2)
attn_pv_h(const __half* __restrict__ P, const __half* __restrict__ Vt,
          __half* __restrict__ O) {
    int bh = blockIdx.y, b = bh >> 4, h = bh & 15;
    int m0 = blockIdx.x * 128;
    const __half* Pb = P + (size_t)bh * S_ * S_;
    const __half* Vb = Vt + (size_t)bh * HD_ * S_;

    extern __shared__ char smem[];
    uint32_t sA = smem_u32(smem);
    uint32_t sB = sA + H_STG * H_STAGE;

    int tid = threadIdx.x;
    int lane = tid & 31, w = tid >> 5;
    int wm = (w & 3) * 32, wn = (w >> 2) * 64;

    int lrow = tid >> 2, lch = tid & 3;
    const __half* gA[2]; const __half* gB[2];
    uint32_t stA[2], stB[2];
#pragma unroll
    for (int rr = 0; rr < 2; rr++) {
        int r = lrow + rr * 64;
        gA[rr] = Pb + (size_t)(m0 + r) * S_ + lch * 8;
        gB[rr] = Vb + (size_t)r * S_ + lch * 8;
        stA[rr] = sA + r * HROWB + lch * 16;
        stB[rr] = sB + r * HROWB + lch * 16;
    }

    uint32_t aAddr = sA + (wm + (lane & 15)) * HROWB + ((lane >> 4) & 1) * 16;
    uint32_t bAddr = sB + (wn + (lane & 7) + 8 * ((lane >> 4) & 1)) * HROWB
                        + ((lane >> 3) & 1) * 16;

    float acc[2][8][4];
#pragma unroll
    for (int i = 0; i < 2; i++)
#pragma unroll
        for (int j = 0; j < 8; j++)
#pragma unroll
            for (int q = 0; q < 4; q++) acc[i][j][q] = 0.f;

    int nk = (m0 + 128) / 32;

#pragma unroll
    for (int s = 0; s < 2; s++) {
#pragma unroll
        for (int rr = 0; rr < 2; rr++) {
            cpa16(stA[rr] + s * H_STAGE, gA[rr] + s * 32);
            cpa16(stB[rr] + s * H_STAGE, gB[rr] + s * 32);
        }
        cpa_commit();
    }

    for (int kt = 0; kt < nk; kt++) {
        cpa_wait1();
        __syncthreads();
        if (kt + 2 < nk) {
            int kb = (kt + 2) * 32;
            uint32_t off = ((kt + 2) % H_STG) * H_STAGE;
#pragma unroll
            for (int rr = 0; rr < 2; rr++) {
                cpa16(stA[rr] + off, gA[rr] + kb);
                cpa16(stB[rr] + off, gB[rr] + kb);
            }
        }
        cpa_commit();

        uint32_t soff = (kt % H_STG) * H_STAGE;
#pragma unroll
        for (int ks = 0; ks < 2; ks++) {
            uint32_t koff = soff + ks * 32;
            uint32_t a[2][4];
            ldsm4(a[0], aAddr + koff);
            ldsm4(a[1], aAddr + koff + 16 * HROWB);
            uint32_t b2[4][4];
#pragma unroll
            for (int jp = 0; jp < 4; jp++)
                ldsm4(b2[jp], bAddr + koff + jp * (16 * HROWB));
#pragma unroll
            for (int im = 0; im < 2; im++)
#pragma unroll
                for (int jn = 0; jn < 8; jn++)
                    mma16h(acc[im][jn], a[im], b2[jn >> 1][(jn & 1) * 2], b2[jn >> 1][(jn & 1) * 2 + 1]);
        }
    }

    int cg = 2 * (lane & 3);
#pragma unroll
    for (int im = 0; im < 2; im++) {
#pragma unroll
        for (int half = 0; half < 2; half++) {
            int m = m0 + wm + im * 16 + (lane >> 2) + half * 8;
            __half* cp = O + (size_t)(b * S_ + m) * H_ + h * HD_ + wn + cg;
#pragma unroll
            for (int jn = 0; jn < 8; jn++)
                *((__half2*)(cp + jn * 8)) =
                    __floats2half2_rn(acc[im][jn][half * 2 + 0], acc[im][jn][half * 2 + 1]);
        }
    }
}

// ==================== router (EXACT fp32 input) ====================
__global__ void router_k(const float* __restrict__ xn2e, const float* __restrict__ Wr) {
    int t = blockIdx.x * (blockDim.x >> 5) + (threadIdx.x >> 5);
    if (t >= T_) return;
    int lane = threadIdx.x & 31;
    const float* xr = xn2e + (size_t)t * H_;
    float s[NE_];
#pragma unroll
    for (int e = 0; e < NE_; e++) s[e] = 0.f;
    for (int j = lane; j < H_; j += 32) {
        float xv = xr[j];
#pragma unroll
        for (int e = 0; e < NE_; e++) s[e] += xv * Wr[e * H_ + j];
    }
#pragma unroll
    for (int e = 0; e < NE_; e++)
        for (int off = 16; off; off >>= 1) s[e] += __shfl_xor_sync(0xffffffffu, s[e], off);
    if (lane == 0) {
        int b0 = 0;
#pragma unroll
        for (int e = 1; e < NE_; e++) if (s[e] > s[b0]) b0 = e;
        int b1 = -1;
#pragma unroll
        for (int e = 0; e < NE_; e++) {
            if (e == b0) continue;
            if (b1 < 0 || s[e] > s[b1]) b1 = e;
        }
        float m = s[b0];
        float e0 = __expf(s[b0] - m), e1 = __expf(s[b1] - m);
        float inv = 1.f / (e0 + e1);
        int pos = atomicAdd(&g_cnt[b0], 1);
        g_tok[b0 * T_ + pos] = t; g_wt[b0 * T_ + pos] = e0 * inv;
        pos = atomicAdd(&g_cnt[b1], 1);
        g_tok[b1 * T_ + pos] = t; g_wt[b1 * T_ + pos] = e1 * inv;
    }
}

// ==================== host ====================
extern "C" void kernel_launch(void* const* d_in, const int* in_sizes, int n_in,
                              void* d_out, int out_size) {
    const float* x    = (const float*)d_in[0];
    const float* Wq   = (const float*)d_in[1];
    const float* Wk   = (const float*)d_in[2];
    const float* Wv   = (const float*)d_in[3];
    const float* Wo   = (const float*)d_in[4];
    const float* wln1 = (const float*)d_in[5];
    const float* wln2 = (const float*)d_in[6];
    const float* Wr   = (const float*)d_in[7];
    const float* Wg   = (const float*)d_in[8];
    const float* Wu   = (const float*)d_in[9];
    const float* Wd   = (const float*)d_in[10];
    float* out = (float*)d_out;

    float *p_hg, *p_rex, *p_wt;
    __half *p_q16, *p_k16, *p_vt16, *p_xn16, *p_ao16, *p_xn216, *p_hg16, *p_w16;
    int *p_tok, *p_cnt;
    cudaGetSymbolAddress((void**)&p_hg,    g_hg);
    cudaGetSymbolAddress((void**)&p_rex,   g_rex);
    cudaGetSymbolAddress((void**)&p_q16,   g_q16);
    cudaGetSymbolAddress((void**)&p_k16,   g_k16);
    cudaGetSymbolAddress((void**)&p_vt16,  g_vt16);
    cudaGetSymbolAddress((void**)&p_xn16,  g_xn16);
    cudaGetSymbolAddress((void**)&p_ao16,  g_ao16);
    cudaGetSymbolAddress((void**)&p_xn216, g_xn216);
    cudaGetSymbolAddress((void**)&p_hg16,  g_hg16);
    cudaGetSymbolAddress((void**)&p_w16,   g_w16);
    cudaGetSymbolAddress((void**)&p_tok,   g_tok);
    cudaGetSymbolAddress((void**)&p_wt,    g_wt);
    cudaGetSymbolAddress((void**)&p_cnt,   g_cnt);

    __half* p_P = (__half*)p_hg;
    __half* p_hgpre = (__half*)p_hg;
    __half* p_hupre = (__half*)p_hg + (size_t)NE_ * T_ * I_;

    static int inited = 0;
    static cudaStream_t s2;
    static cudaEvent_t ev_fork, ev_qkvw, ev_wo, ev_moe;
    if (!inited) {
        cudaFuncSetAttribute(hgemm, cudaFuncAttributeMaxDynamicSharedMemorySize, H_SMEM);
        cudaFuncSetAttribute(attn_score_h, cudaFuncAttributeMaxDynamicSharedMemorySize, H_SMEM);
        cudaFuncSetAttribute(attn_pv_h, cudaFuncAttributeMaxDynamicSharedMemorySize, H_SMEM);
        int pLeast, pGreatest;
        cudaDeviceGetStreamPriorityRange(&pLeast, &pGreatest);
        cudaStreamCreateWithPriority(&s2, cudaStreamNonBlocking, pLeast);
        cudaEventCreateWithFlags(&ev_fork, cudaEventDisableTiming);
        cudaEventCreateWithFlags(&ev_qkvw, cudaEventDisableTiming);
        cudaEventCreateWithFlags(&ev_wo,   cudaEventDisableTiming);
        cudaEventCreateWithFlags(&ev_moe,  cudaEventDisableTiming);
        inited = 1;
    }

    zero_cnt_k<<<1, 32>>>();

    // fork: ALL weight conversions on side stream; main overlaps rmsnorm
    cudaEventRecord(ev_fork, 0);
    cudaStreamWaitEvent(s2, ev_fork, 0);
    cvt16_k<<<1024, 256, 0, s2>>>(Wq, p_w16 + OFF_WQ, (size_t)H_ * H_ / 8);
    cvt16_k<<<1024, 256, 0, s2>>>(Wk, p_w16 + OFF_WK, (size_t)H_ * H_ / 8);
    cvt16_k<<<1024, 256, 0, s2>>>(Wv, p_w16 + OFF_WV, (size_t)H_ * H_ / 8);
    cudaEventRecord(ev_qkvw, s2);
    cvt16_k<<<1024, 256, 0, s2>>>(Wo, p_w16 + OFF_WO, (size_t)H_ * H_ / 8);
    cudaEventRecord(ev_wo, s2);
    cvt16_k<<<4096, 256, 0, s2>>>(Wg, p_w16 + OFF_WG, (size_t)NE_ * I_ * H_ / 8);
    cvt16_k<<<4096, 256, 0, s2>>>(Wu, p_w16 + OFF_WU, (size_t)NE_ * I_ * H_ / 8);
    cvt16_k<<<4096, 256, 0, s2>>>(Wd, p_w16 + OFF_WD, (size_t)NE_ * H_ * I_ / 8);
    cudaEventRecord(ev_moe, s2);

    rmsnorm_k<<<T_, 256>>>(x, wln1, p_xn16, nullptr);

    // join: QKV weights ready
    cudaStreamWaitEvent(0, ev_qkvw, 0);

    // QKV fused: q,k -> fp16 [t][H]; v -> fp16 transposed [b,h][d][s]
    {
        GArgs a = {};
        a.A = p_xn16;
        a.B0 = p_w16 + OFF_WQ; a.B1 = p_w16 + OFF_WK; a.B2 = p_w16 + OFF_WV;
        a.H0 = p_q16; a.H1 = p_k16; a.H2 = p_vt16;
        a.M = T_; a.N = H_; a.K = H_; a.lda = H_; a.ldb = H_; a.ldc = H_;
        a.mode = 0; a.qkv = 1;
        hgemm<<<dim3(H_ / 128, T_ / 128, 3), 256, H_SMEM>>>(a);
    }

    // triangular score grid: 136 lower-triangle tiles per bh
    attn_score_h<<<dim3(136, 1, B_ * NH_), 256, H_SMEM>>>(p_q16, p_k16);
    softmax_k<<<B_ * NH_ * S_, 256>>>(p_P);
    attn_pv_h<<<dim3(S_ / 128, B_ * NH_), 256, H_SMEM>>>(p_P, p_vt16, p_ao16);

    // join: Wo fp16 ready
    cudaStreamWaitEvent(0, ev_wo, 0);

    // Wo projection + fused residual (fp32 out)
    {
        GArgs a = {};
        a.A = p_ao16; a.B0 = p_w16 + OFF_WO; a.C0 = out;
        a.resid = x;
        a.M = T_; a.N = H_; a.K = H_; a.lda = H_; a.ldb = H_; a.ldc = H_;
        a.mode = 0;
        hgemm<<<dim3(H_ / 128, T_ / 128, 1), 256, H_SMEM>>>(a);
    }

    rmsnorm_k<<<T_, 256>>>(out, wln2, p_xn216, p_rex);
    router_k<<<T_ / 8, 256>>>(p_rex, Wr);

    // join: MoE weights fp16 ready
    cudaStreamWaitEvent(0, ev_moe, 0);

    // MoE gate+up (gathered A; fp16 pre-act outputs)
    {
        GArgs a = {};
        a.A = p_xn216;
        a.B0 = p_w16 + OFF_WG; a.B1 = p_w16 + OFF_WU;
        a.H0 = p_hgpre; a.H1 = p_hupre;
        a.M = T_; a.N = I_; a.K = H_; a.lda = H_; a.ldb = H_; a.ldc = I_;
        a.tok = p_tok; a.cntp = p_cnt;
        a.bStride = (size_t)I_ * H_; a.cStride = (size_t)T_ * I_;
        a.mode = 1;
        hgemm<<<dim3(I_ / 128, T_ / 128, 2 * NE_), 256, H_SMEM>>>(a);
    }

    swiglu_all_k<<<dim3(512, NE_), 256>>>(p_hgpre, p_hupre, p_hg16);

    // MoE down: atomic scatter-add into out
    {
        GArgs a = {};
        a.A = p_hg16; a.B0 = p_w16 + OFF_WD; a.C0 = out;
        a.M = T_; a.N = H_; a.K = I_; a.lda = I_; a.ldb = I_; a.ldc = H_;
        a.tok = p_tok; a.wt = p_wt; a.cntp = p_cnt;
        a.aStride = (size_t)T_ * I_; a.bStride = (size_t)H_ * I_;
        a.mode = 2;
        hgemm<<<dim3(H_ / 128, T_ / 128, NE_), 256, H_SMEM>>>(a);
    }
}